// round 17
// baseline (speedup 1.0000x reference)
#include <cuda_runtime.h>
#include <cuda_fp16.h>
#include <cstdint>

#define BATCH   4096
#define IN_DIM  512
#define OUT_DIM 512
#define NG      8
#define KDIM    4096   // IN_DIM * NG
#define KC      64     // K elems per chunk (128B fp16 rows)
#define NC      (KDIM / KC)      // 64 chunks
#define ARR     16384            // one operand tile: 128 rows x 128B
#define STAGE   (2 * ARR)        // {A, B} = 32KB per stage
#define NSTAGE  3
#define DSMEM   (NSTAGE * STAGE) // 96KB

// ---------------- scratch: fp16 W only (A is fused) ----------------
__device__ __align__(128) __half g_B[(size_t)OUT_DIM * KDIM];  // 4MB [j][k]

__device__ __forceinline__ uint32_t cvta_shared(const void* p) {
    uint32_t a;
    asm("{ .reg .u64 t; cvta.to.shared.u64 t, %1; cvt.u32.u64 %0, t; }"
        : "=r"(a) : "l"(p));
    return a;
}

// ---------------- closed-form uniform cubic B-spline -> 8 packed halfs ----------------
// x in cell c = clamp(floor((x+1)*2.5), 0, 4); nonzero bases g = c-3..c with
// weights {(1-t)^3, 3t^3-6t^2+4, -3t^3+3t^2+3t+1, t^3}/6. Out-of-range g drop.
__device__ __forceinline__ uint4 basis8(float xv) {
    float u  = (xv + 1.0f) * 2.5f;
    float cf = floorf(u);
    cf = fminf(fmaxf(cf, 0.0f), 4.0f);
    int   c  = (int)cf;
    float t  = u - cf;

    float t2 = t * t, t3 = t2 * t, omt = 1.0f - t;
    const float s6 = 1.0f / 6.0f;
    uint32_t hw0 = __half_as_ushort(__float2half_rn(omt * omt * omt * s6));
    uint32_t hw1 = __half_as_ushort(__float2half_rn((3.0f * t3 - 6.0f * t2 + 4.0f) * s6));
    uint32_t hw2 = __half_as_ushort(__float2half_rn((-3.0f * t3 + 3.0f * t2 + 3.0f * t + 1.0f) * s6));
    uint32_t hw3 = __half_as_ushort(__float2half_rn(t3 * s6));

    uint32_t o[4];
#pragma unroll
    for (int p = 0; p < 4; p++) {
        int d0 = 2 * p - c + 3, d1 = d0 + 1;
        uint32_t lo = (d0 == 0) ? hw0 : (d0 == 1) ? hw1 : (d0 == 2) ? hw2 : (d0 == 3) ? hw3 : 0u;
        uint32_t hi = (d1 == 0) ? hw0 : (d1 == 1) ? hw1 : (d1 == 2) ? hw2 : (d1 == 3) ? hw3 : 0u;
        o[p] = lo | (hi << 16);
    }
    return make_uint4(o[0], o[1], o[2], o[3]);
}

// ---------------- 1) W = coeff*scaling, transposed to [j][i*8+g], fp16 ----------------
__global__ void build_wt(const float* __restrict__ coeff,
                         const float* __restrict__ scaling) {
    __shared__ float s[32][260];
    int i0 = blockIdx.x * 32, j0 = blockIdx.y * 32;
    for (int l = threadIdx.x; l < 8192; l += 256) {
        int ii = l >> 8, jg = l & 255;
        s[ii][jg] = coeff[(size_t)(i0 + ii) * (OUT_DIM * NG) + j0 * 8 + jg];
    }
    __syncthreads();
    for (int l = threadIdx.x; l < 8192; l += 256) {
        int j = l >> 8, ig = l & 255, ii = ig >> 3, g = ig & 7;
        float v = s[ii][j * 8 + g] * scaling[(size_t)(i0 + ii) * OUT_DIM + j0 + j];
        g_B[(size_t)(j0 + j) * KDIM + (i0 + ii) * 8 + g] = __float2half_rn(v);
    }
}

// ---------------- 2) fused basis + HMMA GEMM ----------------
__device__ __forceinline__ void ldm4(uint32_t& r0, uint32_t& r1, uint32_t& r2,
                                     uint32_t& r3, uint32_t addr) {
    asm volatile("ldmatrix.sync.aligned.m8n8.x4.shared.b16 {%0,%1,%2,%3}, [%4];"
                 : "=r"(r0), "=r"(r1), "=r"(r2), "=r"(r3) : "r"(addr));
}

#define MMA(d, a, b)                                                         \
    asm volatile(                                                            \
        "mma.sync.aligned.m16n8k16.row.col.f32.f16.f16.f32 "                 \
        "{%0,%1,%2,%3}, {%4,%5,%6,%7}, {%8,%9}, {%0,%1,%2,%3};"              \
        : "+f"((d)[0]), "+f"((d)[1]), "+f"((d)[2]), "+f"((d)[3])             \
        : "r"((a)[0]), "r"((a)[1]), "r"((a)[2]), "r"((a)[3]),                \
          "r"((b)[0]), "r"((b)[1]))

__global__ __launch_bounds__(512, 1) void kan_mma(const float* __restrict__ xg,
                                                  float* __restrict__ out) {
    extern __shared__ char dyn[];
    const uint32_t sb = cvta_shared(dyn);

    const int tid = threadIdx.x, wid = tid >> 5, lane = tid & 31;
    const int jbase = blockIdx.x * 128, bbase = blockIdx.y * 128;
    const int m0 = (wid & 3) * 32, n0 = (wid >> 2) * 32;  // 4m x 4n warp grid

    const __half* srcB = g_B + (size_t)jbase * KDIM;

    // ---- B staging (cp.async): per thread 2 x 16B ----
#define ISSUE_B(c, st)                                                        \
    {                                                                         \
        _Pragma("unroll") for (int v = 0; v < 2; v++) {                       \
            int ch = v * 512 + tid;                                           \
            int r = ch >> 3, q = ch & 7;                                      \
            const void* g = srcB + (size_t)r * KDIM + (c) * KC + q * 8;       \
            uint32_t d = sb + (st) * STAGE + ARR + r * 128 +                  \
                         ((q ^ (r & 7)) << 4);                                \
            asm volatile("cp.async.cg.shared.global [%0], [%1], 16;"          \
                         :: "r"(d), "l"(g));                                  \
        }                                                                     \
        asm volatile("cp.async.commit_group;");                               \
    }

    // ---- A staging (fused basis): thread handles rows rA0, rA0+64, i = iiA ----
    const int rA0 = tid >> 3, iiA = tid & 7;
    const uint32_t aswz = (uint32_t)((iiA ^ (rA0 & 7)) << 4);  // (rA0+64)&7 == rA0&7
    const float* xp0 = xg + (size_t)(bbase + rA0) * IN_DIM + iiA;
    const float* xp1 = xp0 + (size_t)64 * IN_DIM;

#define STS_A(x0, x1, st)                                                     \
    {                                                                         \
        uint4 k0 = basis8(x0), k1 = basis8(x1);                               \
        uint32_t d0 = sb + (st) * STAGE + rA0 * 128 + aswz;                   \
        asm volatile("st.shared.v4.b32 [%0], {%1,%2,%3,%4};"                  \
                     :: "r"(d0), "r"(k0.x), "r"(k0.y), "r"(k0.z), "r"(k0.w)   \
                     : "memory");                                             \
        asm volatile("st.shared.v4.b32 [%0], {%1,%2,%3,%4};"                  \
                     :: "r"(d0 + 8192), "r"(k1.x), "r"(k1.y), "r"(k1.z),      \
                        "r"(k1.w) : "memory");                                \
    }

    float acc[2][4][4];
#pragma unroll
    for (int mi = 0; mi < 2; mi++)
#pragma unroll
        for (int nf = 0; nf < 4; nf++)
#pragma unroll
            for (int e = 0; e < 4; e++) acc[mi][nf][e] = 0.0f;

    const int laneA = lane & 15;                         // A: row offset
    const int qA    = lane >> 4;                         // A: 16B k-half
    const int rBl   = (lane & 7) + ((lane >> 4) << 3);   // B: row offset
    const int qB    = (lane >> 3) & 1;                   // B: 16B k-half

    // ---- prologue: chunks 0,1 staged directly; prefetch x for chunk 2 ----
    ISSUE_B(0, 0);
    ISSUE_B(1, 1);
    STS_A(xp0[0 * 8], xp1[0 * 8], 0);
    STS_A(xp0[1 * 8], xp1[1 * 8], 1);
    float xr0 = xp0[2 * 8], xr1 = xp1[2 * 8];

    for (int c = 0; c < NC; c++) {
        if (c + 1 < NC)
            asm volatile("cp.async.wait_group 1;" ::: "memory");   // chunk c landed
        else
            asm volatile("cp.async.wait_group 0;" ::: "memory");   // last chunk
        __syncthreads();                   // publish stage c; slot (c+2)%3 free

        if (c + 2 < NC) {
            ISSUE_B(c + 2, (c + 2) % 3);
            STS_A(xr0, xr1, (c + 2) % 3);  // basis from prefetched x (no LDG stall)
        }
        if (c + 3 < NC) {                  // prefetch x for chunk c+3
            xr0 = xp0[(c + 3) * 8];
            xr1 = xp1[(c + 3) * 8];
        }

        const uint32_t stg = sb + (c % 3) * STAGE;
#pragma unroll
        for (int ks = 0; ks < 4; ks++) {   // 4 x k16 per 64-chunk
            const int q0 = ks * 2;
            uint32_t ah[2][4];
#pragma unroll
            for (int mi = 0; mi < 2; mi++) {
                int r = m0 + mi * 16 + laneA;
                int q = q0 + qA;
                uint32_t sw = r * 128 + ((q ^ (r & 7)) << 4);
                ldm4(ah[mi][0], ah[mi][1], ah[mi][2], ah[mi][3], stg + sw);
            }
            uint32_t bh[4][2];
#pragma unroll
            for (int g = 0; g < 2; g++) {
                int r = n0 + g * 16 + rBl;
                int q = q0 + qB;
                uint32_t sw = r * 128 + ((q ^ (r & 7)) << 4);
                ldm4(bh[2 * g][0], bh[2 * g][1], bh[2 * g + 1][0], bh[2 * g + 1][1],
                     stg + ARR + sw);
            }
#pragma unroll
            for (int mi = 0; mi < 2; mi++)
#pragma unroll
                for (int nf = 0; nf < 4; nf++) MMA(acc[mi][nf], ah[mi], bh[nf]);
        }
    }

    // ---- epilogue: direct float2 stores ----
    const int row  = lane >> 2;
    const int colp = (lane & 3) * 2;
#pragma unroll
    for (int mi = 0; mi < 2; mi++)
#pragma unroll
        for (int nf = 0; nf < 4; nf++) {
            size_t r0o = (size_t)(bbase + m0 + mi * 16 + row) * OUT_DIM +
                         jbase + n0 + nf * 8 + colp;
            *reinterpret_cast<float2*>(&out[r0o]) =
                make_float2(acc[mi][nf][0], acc[mi][nf][1]);
            *reinterpret_cast<float2*>(&out[r0o + 8 * OUT_DIM]) =
                make_float2(acc[mi][nf][2], acc[mi][nf][3]);
        }
}

// ---------------- launch ----------------
extern "C" void kernel_launch(void* const* d_in, const int* in_sizes, int n_in,
                              void* d_out, int out_size) {
    const float* x       = (const float*)d_in[0];   // [4096, 512]
    const float* coeff   = (const float*)d_in[1];   // [512, 512, 8]
    const float* scaling = (const float*)d_in[2];   // [512, 512]
    float* out           = (float*)d_out;           // [4096, 512]
    (void)in_sizes; (void)n_in; (void)out_size;

    cudaFuncSetAttribute(kan_mma, cudaFuncAttributeMaxDynamicSharedMemorySize,
                         DSMEM);

    build_wt<<<dim3(IN_DIM / 32, OUT_DIM / 32), 256>>>(coeff, scaling);
    kan_mma<<<dim3(OUT_DIM / 128, BATCH / 128), 512, DSMEM>>>(x, out);
}